// round 14
// baseline (speedup 1.0000x reference)
#include <cuda_runtime.h>
#include <cuda_fp16.h>
#include <cstdint>
#include <cstddef>

namespace {
constexpr int T = 1000, B = 256, I = 700, H = 256, O = 20, WHS = I + H;
constexpr float DELTA = 0.01f, GAMMA = 0.9f, THETA = 1.0f;
constexpr size_t OFF_LOSS = (size_t)T * B * O;
constexpr size_t OFF_ZF = OFF_LOSS + 1;
constexpr size_t OFF_UF = OFF_ZF + (size_t)B * H;
constexpr size_t OFF_OUF = OFF_UF + (size_t)B * H;

// ---- mma.sync GEMM config ----
constexpr int NCH = 22;
constexpr int WIMG = 256 * 64;
constexpr int GA = 0;
constexpr int GB = 8192;
constexpr int GSTAGE = 24576;
constexpr int GS_TOTAL = 2 * GSTAGE;

// ---- rec fallback smem ----
constexpr int REC_WZ_BYTES = 256 * 256 * 2;
constexpr int REC_SMEM = REC_WZ_BYTES + 2 * 2 * 8 * 4 + 64;

// ---- segmented ou scan ----
constexpr int NSEG = 50, SEGL = 20;
}  // namespace

__device__ __half g_curx[(size_t)T * B * H];   // x @ W_x^T, fp16
__device__ uint32_t g_zmask[(size_t)T * B * 8];
__device__ float g_losspart[(size_t)T * B];
__device__ float g_segend[(size_t)NSEG * B * O];
__device__ float g_carry[(size_t)NSEG * B * O];
__device__ int g_spike_flag;
__device__ __align__(128) unsigned char g_wB[NCH * WIMG];

// ---------------------------------------------------------------------------
// helpers
// ---------------------------------------------------------------------------
__device__ __forceinline__ unsigned smem_u32(const void* p) {
  return (unsigned)__cvta_generic_to_shared(p);
}
__device__ __forceinline__ uint32_t pack_half2(float a, float b) {
  __half2 h = __floats2half2_rn(a, b);
  return *reinterpret_cast<uint32_t*>(&h);
}

#define LDSM4(r, addr)                                                        \
  asm volatile("ldmatrix.sync.aligned.m8n8.x4.shared.b16 {%0,%1,%2,%3}, [%4];" \
               : "=r"((r)[0]), "=r"((r)[1]), "=r"((r)[2]), "=r"((r)[3])        \
               : "r"(addr))

#define MMA16816F(d, a, b0, b1)                                               \
  asm volatile(                                                               \
      "mma.sync.aligned.m16n8k16.row.col.f32.f16.f16.f32 "                    \
      "{%0,%1,%2,%3},{%4,%5,%6,%7},{%8,%9},{%0,%1,%2,%3};"                    \
      : "+f"((d)[0]), "+f"((d)[1]), "+f"((d)[2]), "+f"((d)[3])                \
      : "r"((a)[0]), "r"((a)[1]), "r"((a)[2]), "r"((a)[3]), "r"(b0), "r"(b1))

#define CPASYNC16(dst, src)                                                   \
  asm volatile("cp.async.cg.shared.global [%0], [%1], 16;" :: "r"(dst),       \
               "l"(src) : "memory")

// ---------------------------------------------------------------------------
// Kernel 0: W_h[:, :700] -> fp16, pre-swizzled smem-image layout.
// ---------------------------------------------------------------------------
__global__ void prep_w_kernel(const float* __restrict__ Wh) {
  const int chunk = blockIdx.x;
  const int n = threadIdx.x;
  unsigned char* dst = g_wB + (size_t)chunk * WIMG + n * 64;
#pragma unroll
  for (int c = 0; c < 4; ++c) {
    uint32_t u[4];
#pragma unroll
    for (int jj = 0; jj < 4; ++jj) {
      const int k = chunk * 32 + c * 8 + jj * 2;
      float w0 = (k < I) ? Wh[(size_t)n * WHS + k] : 0.f;
      float w1 = (k + 1 < I) ? Wh[(size_t)n * WHS + k + 1] : 0.f;
      u[jj] = pack_half2(w0, w1);
    }
    const int cSw = c ^ ((n >> 1) & 3);
    *reinterpret_cast<uint4*>(dst + cSw * 16) = make_uint4(u[0], u[1], u[2], u[3]);
  }
}

// ---------------------------------------------------------------------------
// Kernel 1: cur_x = x @ W_x^T via mma.sync fp16; epilogue stores fp16.
// ---------------------------------------------------------------------------
__global__ __launch_bounds__(256, 1) void gemm_mma_kernel(const float* __restrict__ X) {
  extern __shared__ __align__(1024) unsigned char smem[];
  const uint32_t sb = smem_u32(smem);
  const int tid = threadIdx.x;
  const int lane = tid & 31, wid = tid >> 5;
  const int wm = (wid & 1) * 64, wn = (wid >> 1) * 64;
  const int m0 = blockIdx.x * 128;

  const int arow = tid >> 1;
  const int aseg = (tid & 1) << 4;
  const float* xrow = X + (size_t)(m0 + arow) * I;
  const uint32_t aXor = ((arow >> 1) & 3);
  const uint32_t aDst = (uint32_t)(arow * 64);

  int raddr[4], sxa[4], rbad[4], sxb[4];
#pragma unroll
  for (int mt = 0; mt < 4; ++mt) {
    int r = wm + mt * 16 + (lane & 15);
    raddr[mt] = r * 64;
    sxa[mt] = (r >> 1) & 3;
  }
  const int ca = lane >> 4;
#pragma unroll
  for (int g = 0; g < 4; ++g) {
    int n = wn + g * 16 + (lane & 7) + ((lane >> 4) << 3);
    rbad[g] = n * 64;
    sxb[g] = (n >> 1) & 3;
  }
  const int cb = (lane >> 3) & 1;

  float acc[4][8][4];
#pragma unroll
  for (int mt = 0; mt < 4; ++mt)
#pragma unroll
    for (int n8 = 0; n8 < 8; ++n8)
#pragma unroll
      for (int j = 0; j < 4; ++j) acc[mt][n8][j] = 0.f;

  float4 av[4];

#pragma unroll
  for (int i = 0; i < 4; ++i) {
    const int col = aseg + i * 4;
    av[i] = (col < I) ? *reinterpret_cast<const float4*>(xrow + col)
                      : make_float4(0.f, 0.f, 0.f, 0.f);
  }
  {
#pragma unroll
    for (int i = 0; i < 4; ++i)
      CPASYNC16(sb + GB + tid * 16 + i * 4096, g_wB + tid * 16 + i * 4096);
    asm volatile("cp.async.commit_group;" ::: "memory");
  }
  {
#pragma unroll
    for (int half = 0; half < 2; ++half) {
      const float4 p = av[2 * half];
      const float4 q = av[2 * half + 1];
      uint32_t hu[4];
      hu[0] = pack_half2(p.x, p.y);
      hu[1] = pack_half2(p.z, p.w);
      hu[2] = pack_half2(q.x, q.y);
      hu[3] = pack_half2(q.z, q.w);
      const int cc = (aseg >> 3) + half;
      const uint32_t off = aDst + ((uint32_t)(cc ^ aXor) << 4);
      *reinterpret_cast<uint4*>(smem + GA + off) = make_uint4(hu[0], hu[1], hu[2], hu[3]);
    }
  }

  for (int c = 0; c < NCH; ++c) {
    asm volatile("cp.async.wait_group 0;" ::: "memory");
    __syncthreads();

    const int nc = c + 1;
    if (nc < NCH) {
      const uint32_t nst = sb + (nc & 1) * GSTAGE;
      const unsigned char* src = g_wB + (size_t)nc * WIMG;
#pragma unroll
      for (int i = 0; i < 4; ++i)
        CPASYNC16(nst + GB + tid * 16 + i * 4096, src + tid * 16 + i * 4096);
      asm volatile("cp.async.commit_group;" ::: "memory");
      const int colbase = nc * 32 + aseg;
#pragma unroll
      for (int i = 0; i < 4; ++i) {
        const int col = colbase + i * 4;
        av[i] = (col < I) ? *reinterpret_cast<const float4*>(xrow + col)
                          : make_float4(0.f, 0.f, 0.f, 0.f);
      }
    }

    const uint32_t st = sb + (c & 1) * GSTAGE;
#pragma unroll
    for (int k16 = 0; k16 < 2; ++k16) {
      uint32_t ah[4][4], bb[4][4];
      const int kca = k16 * 2 + ca;
      const int kcb = k16 * 2 + cb;
#pragma unroll
      for (int mt = 0; mt < 4; ++mt)
        LDSM4(ah[mt], st + GA + raddr[mt] + (((kca ^ sxa[mt])) << 4));
#pragma unroll
      for (int g = 0; g < 4; ++g)
        LDSM4(bb[g], st + GB + rbad[g] + (((kcb ^ sxb[g])) << 4));
#pragma unroll
      for (int mt = 0; mt < 4; ++mt)
#pragma unroll
        for (int g = 0; g < 4; ++g) {
          MMA16816F(acc[mt][2 * g], ah[mt], bb[g][0], bb[g][1]);
          MMA16816F(acc[mt][2 * g + 1], ah[mt], bb[g][2], bb[g][3]);
        }
    }

    if (nc < NCH) {
      unsigned char* stn = smem + (nc & 1) * GSTAGE;
#pragma unroll
      for (int half = 0; half < 2; ++half) {
        const float4 p = av[2 * half];
        const float4 q = av[2 * half + 1];
        uint32_t hu[4];
        hu[0] = pack_half2(p.x, p.y);
        hu[1] = pack_half2(p.z, p.w);
        hu[2] = pack_half2(q.x, q.y);
        hu[3] = pack_half2(q.z, q.w);
        const int cc = (aseg >> 3) + half;
        const uint32_t off = aDst + ((uint32_t)(cc ^ aXor) << 4);
        *reinterpret_cast<uint4*>(stn + GA + off) = make_uint4(hu[0], hu[1], hu[2], hu[3]);
      }
    }
  }

  // ---- epilogue: acc -> g_curx (fp16) ----
#pragma unroll
  for (int mt = 0; mt < 4; ++mt) {
    const int r0 = m0 + wm + mt * 16 + (lane >> 2);
#pragma unroll
    for (int n8 = 0; n8 < 8; ++n8) {
      const int col = wn + n8 * 8 + (lane & 3) * 2;
      *reinterpret_cast<__half2*>(g_curx + (size_t)r0 * H + col) =
          __floats2half2_rn(acc[mt][n8][0], acc[mt][n8][1]);
      *reinterpret_cast<__half2*>(g_curx + (size_t)(r0 + 8) * H + col) =
          __floats2half2_rn(acc[mt][n8][2], acc[mt][n8][3]);
    }
  }
}

// ---------------------------------------------------------------------------
// Kernel Z: zero the spike masks + flag.
// ---------------------------------------------------------------------------
__global__ void __launch_bounds__(256) zero_kernel() {
  const int idx = blockIdx.x * 256 + threadIdx.x;
  uint4* p = reinterpret_cast<uint4*>(g_zmask);
  if (idx < (int)(T * B * 8 / 4))
    p[idx] = make_uint4(0u, 0u, 0u, 0u);
  if (idx == 0) g_spike_flag = 0;
}

// ---------------------------------------------------------------------------
// Kernel 2a: SPECULATIVE recurrence — thread per (b,h), no barriers.
// fp16 cur stream, prefetch distance 2 blocks (16 outstanding loads).
// ---------------------------------------------------------------------------
__global__ void __launch_bounds__(256)
spec_rec_kernel(const float* __restrict__ omp, const float* __restrict__ bop,
                float* __restrict__ out) {
  const int idx = blockIdx.x * 256 + threadIdx.x;  // b*H + h
  const int h = idx & (H - 1);
  const int b = idx >> 8;

  const float om = fabsf(omp[h]);
  const float dmv = DELTA * om;
  const float pom = (-1.f + sqrtf(1.f - dmv * dmv)) / DELTA;
  const float bcoef = pom - fabsf(bop[h]);  // q == 0 under speculation

  const __half* cp = g_curx + (size_t)b * H + h;
  const size_t stepstride = (size_t)B * H;
  constexpr int NBLK = T / 8;  // 125

  float u = 0.f, v = 0.f;
  int spiked = 0;

  __half h0[8], h1[8], h2[8];
#pragma unroll
  for (int k = 0; k < 8; ++k) h0[k] = cp[(size_t)k * stepstride];
  {
    const __half* p1 = cp + (size_t)8 * stepstride;
#pragma unroll
    for (int k = 0; k < 8; ++k) h1[k] = p1[(size_t)k * stepstride];
  }

  for (int blk = 0; blk < NBLK; ++blk) {
    const int pb = blk + 2;
    if (pb < NBLK) {
      const __half* p2 = cp + (size_t)pb * 8 * stepstride;
#pragma unroll
      for (int k = 0; k < 8; ++k) h2[k] = p2[(size_t)k * stepstride];
    }
#pragma unroll
    for (int k = 0; k < 8; ++k) {
      const float cw = __half2float(h0[k]);
      const float un = u + DELTA * (bcoef * u - om * v + cw);
      const float vn = v + DELTA * (om * un + bcoef * v);
      spiked |= (un - THETA) > 0.f;
      u = un; v = vn;
    }
#pragma unroll
    for (int k = 0; k < 8; ++k) { h0[k] = h1[k]; h1[k] = h2[k]; }
  }

  if (spiked) g_spike_flag = 1;
  out[OFF_UF + (size_t)b * H + h] = u;
  out[OFF_ZF + (size_t)b * H + h] = 0.f;
}

// ---------------------------------------------------------------------------
// Kernel 2b: serial fallback (exact, handles spikes). Early-exits when the
// speculation succeeded.
// ---------------------------------------------------------------------------
__global__ void __launch_bounds__(256, 1)
rec_fallback_kernel(const float* __restrict__ Wh, const float* __restrict__ omp,
                    const float* __restrict__ bop, float* __restrict__ out) {
  if (g_spike_flag == 0) return;
  extern __shared__ unsigned char smrec[];
  __half* Wz = reinterpret_cast<__half*>(smrec);
  uint32_t* zms = reinterpret_cast<uint32_t*>(smrec + REC_WZ_BYTES);

  const int tid = threadIdx.x;
  const int lane = tid & 31;
  const int wq = tid >> 5;
  const int b0 = blockIdx.x * 2;

  {
    const float* src = Wh + (size_t)tid * WHS + I;
#pragma unroll 8
    for (int j = 0; j < 256; ++j) Wz[j * 256 + tid] = __float2half(src[j]);
  }
  if (tid < 32) zms[tid] = 0u;

  const float om = fabsf(omp[tid]);
  const float dmv = DELTA * om;
  const float pom = (-1.f + sqrtf(1.f - dmv * dmv)) / DELTA;
  const float bof = fabsf(bop[tid]);
  float u[2] = {0, 0}, v[2] = {0, 0}, q[2] = {0, 0}, zr[2] = {0, 0};

  __syncthreads();

  for (int t = 0; t < T; ++t) {
    const int cbuf = t & 1, nbuf = cbuf ^ 1;
    const __half* cp = g_curx + ((size_t)t * B + b0) * H + tid;
    float a0 = __half2float(cp[0]), a1 = __half2float(cp[H]);

#pragma unroll
    for (int w = 0; w < 8; ++w) {
      uint32_t m = zms[(cbuf * 2 + 0) * 8 + w];
      while (m) {
        int bp = __ffs(m) - 1; m &= m - 1;
        a0 += __half2float(Wz[((w << 5) + bp) * 256 + tid]);
      }
    }
#pragma unroll
    for (int w = 0; w < 8; ++w) {
      uint32_t m = zms[(cbuf * 2 + 1) * 8 + w];
      while (m) {
        int bp = __ffs(m) - 1; m &= m - 1;
        a1 += __half2float(Wz[((w << 5) + bp) * 256 + tid]);
      }
    }

#pragma unroll
    for (int rr = 0; rr < 2; ++rr) {
      const float cw = rr ? a1 : a0;
      float b = pom - bof - q[rr];
      float un = u[rr] + DELTA * (b * u[rr] - om * v[rr] + cw);
      float vn = v[rr] + DELTA * (om * un + b * v[rr]);
      float z = (un - THETA - q[rr]) > 0.f ? 1.f : 0.f;
      q[rr] = GAMMA * q[rr] + z;
      u[rr] = un; v[rr] = vn; zr[rr] = z;
    }

    const unsigned mk0 = __ballot_sync(0xffffffffu, zr[0] > 0.f);
    const unsigned mk1 = __ballot_sync(0xffffffffu, zr[1] > 0.f);
    if (lane == 0) {
      zms[(nbuf * 2 + 0) * 8 + wq] = mk0;
      zms[(nbuf * 2 + 1) * 8 + wq] = mk1;
      g_zmask[((size_t)t * B + b0) * 8 + wq] = mk0;
      g_zmask[((size_t)t * B + b0 + 1) * 8 + wq] = mk1;
    }
    __syncthreads();
  }

#pragma unroll
  for (int rr = 0; rr < 2; ++rr) {
    const size_t idx = (size_t)(b0 + rr) * H + tid;
    out[OFF_ZF + idx] = zr[rr];
    out[OFF_UF + idx] = u[rr];
  }
}

// ---------------------------------------------------------------------------
// Kernel 3a: segment-local ou scan (unchanged).
// ---------------------------------------------------------------------------
__global__ void __launch_bounds__(256, 1)
scan_seg_kernel(const float* __restrict__ Wo, const float* __restrict__ taup,
                float* __restrict__ out) {
  __shared__ float WoT[256 * 20 + 32];
  const int tid = threadIdx.x;
  for (int i = tid; i < 256 * 20; i += 256) {
    const int j = i / 20, o = i - j * 20;
    WoT[i] = Wo[o * H + j];
  }
  __syncthreads();

  const int lid = tid & 31;
  const int gw = blockIdx.x * 8 + (tid >> 5);
  const int b = gw & (B - 1);
  const int seg = gw >> 8;
  const int t0 = seg * SEGL;
  const float alpha = (lid < 20) ? expf(-DELTA / taup[lid]) : 0.f;
  const float onem = 1.f - alpha;
  float l = 0.f;

  uint32_t mw = (lid < 8) ? g_zmask[((size_t)t0 * B + b) * 8 + lid] : 0u;
  for (int k = 0; k < SEGL; ++k) {
    const int t = t0 + k;
    uint32_t mwn = 0u;
    if (k + 1 < SEGL && lid < 8)
      mwn = g_zmask[((size_t)(t + 1) * B + b) * 8 + lid];
    float s = 0.f;
#pragma unroll
    for (int w = 0; w < 8; ++w) {
      uint32_t word = __shfl_sync(0xffffffffu, mw, w);
      while (word) {
        int bp = __ffs(word) - 1; word &= word - 1;
        s += WoT[((w << 5) + bp) * 20 + lid];
      }
    }
    l = alpha * l + onem * s;
    if (lid < 20) out[((size_t)t * B + b) * O + lid] = l;
    mw = mwn;
  }
  if (lid < 20) g_segend[((size_t)seg * B + b) * O + lid] = l;
}

// ---------------------------------------------------------------------------
// Kernel 3b: serial carry over segments, writes ouf.
// ---------------------------------------------------------------------------
__global__ void __launch_bounds__(256)
carry_kernel(const float* __restrict__ taup, float* __restrict__ out) {
  const int idx = blockIdx.x * 256 + threadIdx.x;
  if (idx >= B * O) return;
  const int b = idx / O, o = idx - b * O;
  const float aL = expf(-DELTA * (float)SEGL / taup[o]);
  float c = 0.f;
  for (int s = 0; s < NSEG; ++s) {
    g_carry[((size_t)s * B + b) * O + o] = c;
    c = c * aL + g_segend[((size_t)s * B + b) * O + o];
  }
  out[OFF_OUF + (size_t)b * O + o] = c;
}

// ---------------------------------------------------------------------------
// Kernel 3c: fixup — out[t,b,o] += alpha^(k+1) * carry (skip if 0).
// ---------------------------------------------------------------------------
__global__ void __launch_bounds__(256)
fixup_kernel(const float* __restrict__ taup, float* __restrict__ out) {
  const int idx = blockIdx.x * 256 + threadIdx.x;
  if (idx >= T * B * O) return;
  const int o = idx % O;
  const int tb = idx / O;
  const int t = tb / B, b = tb - t * B;
  const int seg = t / SEGL, k = t - seg * SEGL;
  const float c = g_carry[((size_t)seg * B + b) * O + o];
  if (c != 0.f) {
    const float alpha = expf(-DELTA / taup[o]);
    out[idx] += powf(alpha, (float)(k + 1)) * c;
  }
}

// ---------------------------------------------------------------------------
// Kernel 4: per-(t,b) log-softmax loss partials.
// ---------------------------------------------------------------------------
__global__ void __launch_bounds__(256)
loss_kernel(const int* __restrict__ Y, const float* __restrict__ out) {
  const int idx = blockIdx.x * 256 + threadIdx.x;
  if (idx >= T * B) return;
  const float* o20 = out + (size_t)idx * O;
  const int y = Y[idx];
  float m = -1e30f;
#pragma unroll
  for (int o = 0; o < O; ++o) m = fmaxf(m, o20[o]);
  float se = 0.f;
#pragma unroll
  for (int o = 0; o < O; ++o) se += expf(o20[o] - m);
  g_losspart[idx] = -(o20[y] - m - logf(se)) * (1.f / (float)B);
}

// ---------------------------------------------------------------------------
// Kernel 5: deterministic loss reduction.
// ---------------------------------------------------------------------------
__global__ void __launch_bounds__(1024) reduce_kernel(float* __restrict__ out) {
  __shared__ float s[1024];
  float acc = 0.f;
  for (int i = threadIdx.x; i < T * B; i += 1024) acc += g_losspart[i];
  s[threadIdx.x] = acc;
  __syncthreads();
  for (int st = 512; st > 0; st >>= 1) {
    if (threadIdx.x < st) s[threadIdx.x] += s[threadIdx.x + st];
    __syncthreads();
  }
  if (threadIdx.x == 0) out[OFF_LOSS] = s[0];
}

// ---------------------------------------------------------------------------
extern "C" void kernel_launch(void* const* d_in, const int* in_sizes, int n_in,
                              void* d_out, int out_size) {
  const float* x = (const float*)d_in[0];
  const int* y = (const int*)d_in[1];
  const float* Wh = (const float*)d_in[2];
  const float* omega = (const float*)d_in[3];
  const float* boff = (const float*)d_in[4];
  const float* Wo = (const float*)d_in[5];
  const float* tau = (const float*)d_in[6];
  float* out = (float*)d_out;

  cudaFuncSetAttribute(gemm_mma_kernel, cudaFuncAttributeMaxDynamicSharedMemorySize,
                       GS_TOTAL);
  cudaFuncSetAttribute(rec_fallback_kernel, cudaFuncAttributeMaxDynamicSharedMemorySize,
                       REC_SMEM);

  prep_w_kernel<<<NCH, 256>>>(Wh);
  gemm_mma_kernel<<<(T * B) / 128, 256, GS_TOTAL>>>(x);
  zero_kernel<<<(T * B * 8 / 4 + 255) / 256, 256>>>();
  spec_rec_kernel<<<B * H / 256, 256>>>(omega, boff, out);
  rec_fallback_kernel<<<B / 2, 256, REC_SMEM>>>(Wh, omega, boff, out);
  scan_seg_kernel<<<NSEG * B / 8, 256>>>(Wo, tau, out);
  carry_kernel<<<(B * O + 255) / 256, 256>>>(tau, out);
  fixup_kernel<<<(T * B * O + 255) / 256, 256>>>(tau, out);
  loss_kernel<<<(T * B + 255) / 256, 256>>>(y, out);
  reduce_kernel<<<1, 1024>>>(out);
}

// round 15
// speedup vs baseline: 1.2712x; 1.2712x over previous
#include <cuda_runtime.h>
#include <cuda_fp16.h>
#include <cstdint>
#include <cstddef>

namespace {
constexpr int T = 1000, B = 256, I = 700, H = 256, O = 20, WHS = I + H;
constexpr float DELTA = 0.01f, GAMMA = 0.9f, THETA = 1.0f;
constexpr size_t OFF_LOSS = (size_t)T * B * O;
constexpr size_t OFF_ZF = OFF_LOSS + 1;
constexpr size_t OFF_UF = OFF_ZF + (size_t)B * H;
constexpr size_t OFF_OUF = OFF_UF + (size_t)B * H;

// ---- mma.sync GEMM config ----
constexpr int NCH = 22;
constexpr int WIMG = 256 * 64;
constexpr int GA = 0;
constexpr int GB = 8192;
constexpr int GSTAGE = 24576;
constexpr int GS_TOTAL = 2 * GSTAGE;

// ---- rec fallback smem ----
constexpr int REC_WZ_BYTES = 256 * 256 * 2;
constexpr int REC_SMEM = REC_WZ_BYTES + 2 * 2 * 8 * 4 + 64;

// ---- spec rec staging ----
constexpr int STILE = 40;                    // timesteps per tile
constexpr int SNT = T / STILE;               // 25
constexpr int STILE_BYTES = STILE * H * 2;   // 20480
constexpr int SPEC_SMEM = 2 * STILE_BYTES;   // 40960

// ---- segmented ou scan ----
constexpr int NSEG = 50, SEGL = 20;
}  // namespace

__device__ __align__(128) __half g_curx[(size_t)T * B * H];   // x @ W_x^T, fp16
__device__ uint32_t g_zmask[(size_t)T * B * 8];
__device__ float g_losspart[(size_t)T * B];
__device__ float g_segend[(size_t)NSEG * B * O];
__device__ float g_carry[(size_t)NSEG * B * O];
__device__ int g_spike_flag;
__device__ __align__(128) unsigned char g_wB[NCH * WIMG];

// ---------------------------------------------------------------------------
// helpers
// ---------------------------------------------------------------------------
__device__ __forceinline__ unsigned smem_u32(const void* p) {
  return (unsigned)__cvta_generic_to_shared(p);
}
__device__ __forceinline__ uint32_t pack_half2(float a, float b) {
  __half2 h = __floats2half2_rn(a, b);
  return *reinterpret_cast<uint32_t*>(&h);
}

#define LDSM4(r, addr)                                                        \
  asm volatile("ldmatrix.sync.aligned.m8n8.x4.shared.b16 {%0,%1,%2,%3}, [%4];" \
               : "=r"((r)[0]), "=r"((r)[1]), "=r"((r)[2]), "=r"((r)[3])        \
               : "r"(addr))

#define MMA16816F(d, a, b0, b1)                                               \
  asm volatile(                                                               \
      "mma.sync.aligned.m16n8k16.row.col.f32.f16.f16.f32 "                    \
      "{%0,%1,%2,%3},{%4,%5,%6,%7},{%8,%9},{%0,%1,%2,%3};"                    \
      : "+f"((d)[0]), "+f"((d)[1]), "+f"((d)[2]), "+f"((d)[3])                \
      : "r"((a)[0]), "r"((a)[1]), "r"((a)[2]), "r"((a)[3]), "r"(b0), "r"(b1))

#define CPASYNC16(dst, src)                                                   \
  asm volatile("cp.async.cg.shared.global [%0], [%1], 16;" :: "r"(dst),       \
               "l"(src) : "memory")

// ---------------------------------------------------------------------------
// Kernel 0: W_h[:, :700] -> fp16, pre-swizzled smem-image layout.
// ---------------------------------------------------------------------------
__global__ void prep_w_kernel(const float* __restrict__ Wh) {
  const int chunk = blockIdx.x;
  const int n = threadIdx.x;
  unsigned char* dst = g_wB + (size_t)chunk * WIMG + n * 64;
#pragma unroll
  for (int c = 0; c < 4; ++c) {
    uint32_t u[4];
#pragma unroll
    for (int jj = 0; jj < 4; ++jj) {
      const int k = chunk * 32 + c * 8 + jj * 2;
      float w0 = (k < I) ? Wh[(size_t)n * WHS + k] : 0.f;
      float w1 = (k + 1 < I) ? Wh[(size_t)n * WHS + k + 1] : 0.f;
      u[jj] = pack_half2(w0, w1);
    }
    const int cSw = c ^ ((n >> 1) & 3);
    *reinterpret_cast<uint4*>(dst + cSw * 16) = make_uint4(u[0], u[1], u[2], u[3]);
  }
}

// ---------------------------------------------------------------------------
// Kernel 1: cur_x = x @ W_x^T via mma.sync fp16; epilogue stores fp16.
// ---------------------------------------------------------------------------
__global__ __launch_bounds__(256, 1) void gemm_mma_kernel(const float* __restrict__ X) {
  extern __shared__ __align__(1024) unsigned char smem[];
  const uint32_t sb = smem_u32(smem);
  const int tid = threadIdx.x;
  const int lane = tid & 31, wid = tid >> 5;
  const int wm = (wid & 1) * 64, wn = (wid >> 1) * 64;
  const int m0 = blockIdx.x * 128;

  const int arow = tid >> 1;
  const int aseg = (tid & 1) << 4;
  const float* xrow = X + (size_t)(m0 + arow) * I;
  const uint32_t aXor = ((arow >> 1) & 3);
  const uint32_t aDst = (uint32_t)(arow * 64);

  int raddr[4], sxa[4], rbad[4], sxb[4];
#pragma unroll
  for (int mt = 0; mt < 4; ++mt) {
    int r = wm + mt * 16 + (lane & 15);
    raddr[mt] = r * 64;
    sxa[mt] = (r >> 1) & 3;
  }
  const int ca = lane >> 4;
#pragma unroll
  for (int g = 0; g < 4; ++g) {
    int n = wn + g * 16 + (lane & 7) + ((lane >> 4) << 3);
    rbad[g] = n * 64;
    sxb[g] = (n >> 1) & 3;
  }
  const int cb = (lane >> 3) & 1;

  float acc[4][8][4];
#pragma unroll
  for (int mt = 0; mt < 4; ++mt)
#pragma unroll
    for (int n8 = 0; n8 < 8; ++n8)
#pragma unroll
      for (int j = 0; j < 4; ++j) acc[mt][n8][j] = 0.f;

  float4 av[4];

#pragma unroll
  for (int i = 0; i < 4; ++i) {
    const int col = aseg + i * 4;
    av[i] = (col < I) ? *reinterpret_cast<const float4*>(xrow + col)
                      : make_float4(0.f, 0.f, 0.f, 0.f);
  }
  {
#pragma unroll
    for (int i = 0; i < 4; ++i)
      CPASYNC16(sb + GB + tid * 16 + i * 4096, g_wB + tid * 16 + i * 4096);
    asm volatile("cp.async.commit_group;" ::: "memory");
  }
  {
#pragma unroll
    for (int half = 0; half < 2; ++half) {
      const float4 p = av[2 * half];
      const float4 q = av[2 * half + 1];
      uint32_t hu[4];
      hu[0] = pack_half2(p.x, p.y);
      hu[1] = pack_half2(p.z, p.w);
      hu[2] = pack_half2(q.x, q.y);
      hu[3] = pack_half2(q.z, q.w);
      const int cc = (aseg >> 3) + half;
      const uint32_t off = aDst + ((uint32_t)(cc ^ aXor) << 4);
      *reinterpret_cast<uint4*>(smem + GA + off) = make_uint4(hu[0], hu[1], hu[2], hu[3]);
    }
  }

  for (int c = 0; c < NCH; ++c) {
    asm volatile("cp.async.wait_group 0;" ::: "memory");
    __syncthreads();

    const int nc = c + 1;
    if (nc < NCH) {
      const uint32_t nst = sb + (nc & 1) * GSTAGE;
      const unsigned char* src = g_wB + (size_t)nc * WIMG;
#pragma unroll
      for (int i = 0; i < 4; ++i)
        CPASYNC16(nst + GB + tid * 16 + i * 4096, src + tid * 16 + i * 4096);
      asm volatile("cp.async.commit_group;" ::: "memory");
      const int colbase = nc * 32 + aseg;
#pragma unroll
      for (int i = 0; i < 4; ++i) {
        const int col = colbase + i * 4;
        av[i] = (col < I) ? *reinterpret_cast<const float4*>(xrow + col)
                          : make_float4(0.f, 0.f, 0.f, 0.f);
      }
    }

    const uint32_t st = sb + (c & 1) * GSTAGE;
#pragma unroll
    for (int k16 = 0; k16 < 2; ++k16) {
      uint32_t ah[4][4], bb[4][4];
      const int kca = k16 * 2 + ca;
      const int kcb = k16 * 2 + cb;
#pragma unroll
      for (int mt = 0; mt < 4; ++mt)
        LDSM4(ah[mt], st + GA + raddr[mt] + (((kca ^ sxa[mt])) << 4));
#pragma unroll
      for (int g = 0; g < 4; ++g)
        LDSM4(bb[g], st + GB + rbad[g] + (((kcb ^ sxb[g])) << 4));
#pragma unroll
      for (int mt = 0; mt < 4; ++mt)
#pragma unroll
        for (int g = 0; g < 4; ++g) {
          MMA16816F(acc[mt][2 * g], ah[mt], bb[g][0], bb[g][1]);
          MMA16816F(acc[mt][2 * g + 1], ah[mt], bb[g][2], bb[g][3]);
        }
    }

    if (nc < NCH) {
      unsigned char* stn = smem + (nc & 1) * GSTAGE;
#pragma unroll
      for (int half = 0; half < 2; ++half) {
        const float4 p = av[2 * half];
        const float4 q = av[2 * half + 1];
        uint32_t hu[4];
        hu[0] = pack_half2(p.x, p.y);
        hu[1] = pack_half2(p.z, p.w);
        hu[2] = pack_half2(q.x, q.y);
        hu[3] = pack_half2(q.z, q.w);
        const int cc = (aseg >> 3) + half;
        const uint32_t off = aDst + ((uint32_t)(cc ^ aXor) << 4);
        *reinterpret_cast<uint4*>(stn + GA + off) = make_uint4(hu[0], hu[1], hu[2], hu[3]);
      }
    }
  }

  // ---- epilogue: acc -> g_curx (fp16) ----
#pragma unroll
  for (int mt = 0; mt < 4; ++mt) {
    const int r0 = m0 + wm + mt * 16 + (lane >> 2);
#pragma unroll
    for (int n8 = 0; n8 < 8; ++n8) {
      const int col = wn + n8 * 8 + (lane & 3) * 2;
      *reinterpret_cast<__half2*>(g_curx + (size_t)r0 * H + col) =
          __floats2half2_rn(acc[mt][n8][0], acc[mt][n8][1]);
      *reinterpret_cast<__half2*>(g_curx + (size_t)(r0 + 8) * H + col) =
          __floats2half2_rn(acc[mt][n8][2], acc[mt][n8][3]);
    }
  }
}

// ---------------------------------------------------------------------------
// Kernel Z: reset the spike flag (zmask is only read when the fallback ran,
// and the fallback writes every word itself — no pre-zero needed).
// ---------------------------------------------------------------------------
__global__ void flag_reset_kernel() { g_spike_flag = 0; }

// ---------------------------------------------------------------------------
// Kernel 2a: SPECULATIVE recurrence — CTA per batch row, cp.async staging.
// Tiles of 40 timesteps (20 KB) double-buffered; coalesced 16B/lane loads.
// ---------------------------------------------------------------------------
__global__ void __launch_bounds__(256, 1)
spec_rec_kernel(const float* __restrict__ omp, const float* __restrict__ bop,
                float* __restrict__ out) {
  extern __shared__ __align__(16) unsigned char ssm[];
  const uint32_t sb = smem_u32(ssm);
  const int tid = threadIdx.x;
  const int b = blockIdx.x;

  const float om = fabsf(omp[tid]);
  const float dmv = DELTA * om;
  const float pom = (-1.f + sqrtf(1.f - dmv * dmv)) / DELTA;
  const float bcoef = pom - fabsf(bop[tid]);  // q == 0 under speculation

  const unsigned char* base =
      reinterpret_cast<const unsigned char*>(g_curx) + (size_t)b * H * 2;
  const size_t rowb = (size_t)B * H * 2;  // bytes per timestep row

  // issue one tile's cp.async loads (20480 B = 256 thr x 5 x 16 B)
  auto issue = [&](int tile, int buf) {
    const unsigned char* src = base + (size_t)tile * STILE * rowb;
#pragma unroll
    for (int p = 0; p < 5; ++p) {
      const int o = (p * 256 + tid) * 16;
      const int s = o >> 9, byt = o & 511;
      CPASYNC16(sb + buf * STILE_BYTES + o, src + (size_t)s * rowb + byt);
    }
    asm volatile("cp.async.commit_group;" ::: "memory");
  };

  issue(0, 0);
  float u = 0.f, v = 0.f, umax = -1e30f;

  for (int tile = 0; tile < SNT; ++tile) {
    if (tile + 1 < SNT) {
      issue(tile + 1, (tile + 1) & 1);
      asm volatile("cp.async.wait_group 1;" ::: "memory");
    } else {
      asm volatile("cp.async.wait_group 0;" ::: "memory");
    }
    __syncthreads();
    const __half* hs =
        reinterpret_cast<const __half*>(ssm + (tile & 1) * STILE_BYTES);
#pragma unroll 8
    for (int s = 0; s < STILE; ++s) {
      const float cw = __half2float(hs[s * H + tid]);
      const float un = u + DELTA * (bcoef * u - om * v + cw);
      const float vn = v + DELTA * (om * un + bcoef * v);
      umax = fmaxf(umax, un);
      u = un; v = vn;
    }
    __syncthreads();  // protect buffer before tile+2 overwrites it
  }

  if ((umax - THETA) > 0.f) g_spike_flag = 1;
  out[OFF_UF + (size_t)b * H + tid] = u;
  out[OFF_ZF + (size_t)b * H + tid] = 0.f;
}

// ---------------------------------------------------------------------------
// Kernel 2b: serial fallback (exact, handles spikes). Early-exits when the
// speculation succeeded. Writes every zmask word itself.
// ---------------------------------------------------------------------------
__global__ void __launch_bounds__(256, 1)
rec_fallback_kernel(const float* __restrict__ Wh, const float* __restrict__ omp,
                    const float* __restrict__ bop, float* __restrict__ out) {
  if (g_spike_flag == 0) return;
  extern __shared__ unsigned char smrec[];
  __half* Wz = reinterpret_cast<__half*>(smrec);
  uint32_t* zms = reinterpret_cast<uint32_t*>(smrec + REC_WZ_BYTES);

  const int tid = threadIdx.x;
  const int lane = tid & 31;
  const int wq = tid >> 5;
  const int b0 = blockIdx.x * 2;

  {
    const float* src = Wh + (size_t)tid * WHS + I;
#pragma unroll 8
    for (int j = 0; j < 256; ++j) Wz[j * 256 + tid] = __float2half(src[j]);
  }
  if (tid < 32) zms[tid] = 0u;

  const float om = fabsf(omp[tid]);
  const float dmv = DELTA * om;
  const float pom = (-1.f + sqrtf(1.f - dmv * dmv)) / DELTA;
  const float bof = fabsf(bop[tid]);
  float u[2] = {0, 0}, v[2] = {0, 0}, q[2] = {0, 0}, zr[2] = {0, 0};

  __syncthreads();

  for (int t = 0; t < T; ++t) {
    const int cbuf = t & 1, nbuf = cbuf ^ 1;
    const __half* cp = g_curx + ((size_t)t * B + b0) * H + tid;
    float a0 = __half2float(cp[0]), a1 = __half2float(cp[H]);

#pragma unroll
    for (int w = 0; w < 8; ++w) {
      uint32_t m = zms[(cbuf * 2 + 0) * 8 + w];
      while (m) {
        int bp = __ffs(m) - 1; m &= m - 1;
        a0 += __half2float(Wz[((w << 5) + bp) * 256 + tid]);
      }
    }
#pragma unroll
    for (int w = 0; w < 8; ++w) {
      uint32_t m = zms[(cbuf * 2 + 1) * 8 + w];
      while (m) {
        int bp = __ffs(m) - 1; m &= m - 1;
        a1 += __half2float(Wz[((w << 5) + bp) * 256 + tid]);
      }
    }

#pragma unroll
    for (int rr = 0; rr < 2; ++rr) {
      const float cw = rr ? a1 : a0;
      float b = pom - bof - q[rr];
      float un = u[rr] + DELTA * (b * u[rr] - om * v[rr] + cw);
      float vn = v[rr] + DELTA * (om * un + b * v[rr]);
      float z = (un - THETA - q[rr]) > 0.f ? 1.f : 0.f;
      q[rr] = GAMMA * q[rr] + z;
      u[rr] = un; v[rr] = vn; zr[rr] = z;
    }

    const unsigned mk0 = __ballot_sync(0xffffffffu, zr[0] > 0.f);
    const unsigned mk1 = __ballot_sync(0xffffffffu, zr[1] > 0.f);
    if (lane == 0) {
      zms[(nbuf * 2 + 0) * 8 + wq] = mk0;
      zms[(nbuf * 2 + 1) * 8 + wq] = mk1;
      g_zmask[((size_t)t * B + b0) * 8 + wq] = mk0;
      g_zmask[((size_t)t * B + b0 + 1) * 8 + wq] = mk1;
    }
    __syncthreads();
  }

#pragma unroll
  for (int rr = 0; rr < 2; ++rr) {
    const size_t idx = (size_t)(b0 + rr) * H + tid;
    out[OFF_ZF + idx] = zr[rr];
    out[OFF_UF + idx] = u[rr];
  }
}

// ---------------------------------------------------------------------------
// Kernel 3a: segment-local ou scan; zero fast path when no spikes.
// ---------------------------------------------------------------------------
__global__ void __launch_bounds__(256, 1)
scan_seg_kernel(const float* __restrict__ Wo, const float* __restrict__ taup,
                float* __restrict__ out) {
  const int tid = threadIdx.x;
  const int lid = tid & 31;
  const int gw = blockIdx.x * 8 + (tid >> 5);
  const int b = gw & (B - 1);
  const int seg = gw >> 8;
  const int t0 = seg * SEGL;

  if (g_spike_flag == 0) {  // uniform branch: bit-exact zero outputs
    if (lid < 20) {
      for (int k = 0; k < SEGL; ++k)
        out[((size_t)(t0 + k) * B + b) * O + lid] = 0.f;
      g_segend[((size_t)seg * B + b) * O + lid] = 0.f;
    }
    return;
  }

  __shared__ float WoT[256 * 20 + 32];
  for (int i = tid; i < 256 * 20; i += 256) {
    const int j = i / 20, o = i - j * 20;
    WoT[i] = Wo[o * H + j];
  }
  __syncthreads();

  const float alpha = (lid < 20) ? expf(-DELTA / taup[lid]) : 0.f;
  const float onem = 1.f - alpha;
  float l = 0.f;

  uint32_t mw = (lid < 8) ? g_zmask[((size_t)t0 * B + b) * 8 + lid] : 0u;
  for (int k = 0; k < SEGL; ++k) {
    const int t = t0 + k;
    uint32_t mwn = 0u;
    if (k + 1 < SEGL && lid < 8)
      mwn = g_zmask[((size_t)(t + 1) * B + b) * 8 + lid];
    float s = 0.f;
#pragma unroll
    for (int w = 0; w < 8; ++w) {
      uint32_t word = __shfl_sync(0xffffffffu, mw, w);
      while (word) {
        int bp = __ffs(word) - 1; word &= word - 1;
        s += WoT[((w << 5) + bp) * 20 + lid];
      }
    }
    l = alpha * l + onem * s;
    if (lid < 20) out[((size_t)t * B + b) * O + lid] = l;
    mw = mwn;
  }
  if (lid < 20) g_segend[((size_t)seg * B + b) * O + lid] = l;
}

// ---------------------------------------------------------------------------
// Kernel 3b: serial carry over segments, writes ouf. Zero fast path.
// ---------------------------------------------------------------------------
__global__ void __launch_bounds__(256)
carry_kernel(const float* __restrict__ taup, float* __restrict__ out) {
  const int idx = blockIdx.x * 256 + threadIdx.x;
  if (idx >= B * O) return;
  if (g_spike_flag == 0) {
    out[OFF_OUF + idx] = 0.f;
    return;
  }
  const int b = idx / O, o = idx - b * O;
  const float aL = expf(-DELTA * (float)SEGL / taup[o]);
  float c = 0.f;
  for (int s = 0; s < NSEG; ++s) {
    g_carry[((size_t)s * B + b) * O + o] = c;
    c = c * aL + g_segend[((size_t)s * B + b) * O + o];
  }
  out[OFF_OUF + (size_t)b * O + o] = c;
}

// ---------------------------------------------------------------------------
// Kernel 3c: fixup — no-op when no spikes (carry all zero).
// ---------------------------------------------------------------------------
__global__ void __launch_bounds__(256)
fixup_kernel(const float* __restrict__ taup, float* __restrict__ out) {
  if (g_spike_flag == 0) return;
  const int idx = blockIdx.x * 256 + threadIdx.x;
  if (idx >= T * B * O) return;
  const int o = idx % O;
  const int tb = idx / O;
  const int t = tb / B, b = tb - t * B;
  const int seg = t / SEGL, k = t - seg * SEGL;
  const float c = g_carry[((size_t)seg * B + b) * O + o];
  if (c != 0.f) {
    const float alpha = expf(-DELTA / taup[o]);
    out[idx] += powf(alpha, (float)(k + 1)) * c;
  }
}

// ---------------------------------------------------------------------------
// Kernel 4: per-(t,b) log-softmax loss partials; constant fast path
// (bit-exact: log-softmax of the all-zero row is -log(20)).
// ---------------------------------------------------------------------------
__global__ void __launch_bounds__(256)
loss_kernel(const int* __restrict__ Y, const float* __restrict__ out) {
  const int idx = blockIdx.x * 256 + threadIdx.x;
  if (idx >= T * B) return;
  if (g_spike_flag == 0) {
    g_losspart[idx] = logf(20.f) * (1.f / (float)B);
    return;
  }
  const float* o20 = out + (size_t)idx * O;
  const int y = Y[idx];
  float m = -1e30f;
#pragma unroll
  for (int o = 0; o < O; ++o) m = fmaxf(m, o20[o]);
  float se = 0.f;
#pragma unroll
  for (int o = 0; o < O; ++o) se += expf(o20[o] - m);
  g_losspart[idx] = -(o20[y] - m - logf(se)) * (1.f / (float)B);
}

// ---------------------------------------------------------------------------
// Kernel 5: deterministic loss reduction.
// ---------------------------------------------------------------------------
__global__ void __launch_bounds__(1024) reduce_kernel(float* __restrict__ out) {
  __shared__ float s[1024];
  float acc = 0.f;
  for (int i = threadIdx.x; i < T * B; i += 1024) acc += g_losspart[i];
  s[threadIdx.x] = acc;
  __syncthreads();
  for (int st = 512; st > 0; st >>= 1) {
    if (threadIdx.x < st) s[threadIdx.x] += s[threadIdx.x + st];
    __syncthreads();
  }
  if (threadIdx.x == 0) out[OFF_LOSS] = s[0];
}

// ---------------------------------------------------------------------------
extern "C" void kernel_launch(void* const* d_in, const int* in_sizes, int n_in,
                              void* d_out, int out_size) {
  const float* x = (const float*)d_in[0];
  const int* y = (const int*)d_in[1];
  const float* Wh = (const float*)d_in[2];
  const float* omega = (const float*)d_in[3];
  const float* boff = (const float*)d_in[4];
  const float* Wo = (const float*)d_in[5];
  const float* tau = (const float*)d_in[6];
  float* out = (float*)d_out;

  cudaFuncSetAttribute(gemm_mma_kernel, cudaFuncAttributeMaxDynamicSharedMemorySize,
                       GS_TOTAL);
  cudaFuncSetAttribute(rec_fallback_kernel, cudaFuncAttributeMaxDynamicSharedMemorySize,
                       REC_SMEM);
  cudaFuncSetAttribute(spec_rec_kernel, cudaFuncAttributeMaxDynamicSharedMemorySize,
                       SPEC_SMEM);

  prep_w_kernel<<<NCH, 256>>>(Wh);
  gemm_mma_kernel<<<(T * B) / 128, 256, GS_TOTAL>>>(x);
  flag_reset_kernel<<<1, 1>>>();
  spec_rec_kernel<<<B, 256, SPEC_SMEM>>>(omega, boff, out);
  rec_fallback_kernel<<<B / 2, 256, REC_SMEM>>>(Wh, omega, boff, out);
  scan_seg_kernel<<<NSEG * B / 8, 256>>>(Wo, tau, out);
  carry_kernel<<<(B * O + 255) / 256, 256>>>(tau, out);
  fixup_kernel<<<(T * B * O + 255) / 256, 256>>>(tau, out);
  loss_kernel<<<(T * B + 255) / 256, 256>>>(y, out);
  reduce_kernel<<<1, 1024>>>(out);
}

// round 16
// speedup vs baseline: 1.3532x; 1.0644x over previous
#include <cuda_runtime.h>
#include <cuda_fp16.h>
#include <cstdint>
#include <cstddef>

namespace {
constexpr int T = 1000, B = 256, I = 700, H = 256, O = 20, WHS = I + H;
constexpr float DELTA = 0.01f, GAMMA = 0.9f, THETA = 1.0f;
constexpr size_t OFF_LOSS = (size_t)T * B * O;
constexpr size_t OFF_ZF = OFF_LOSS + 1;
constexpr size_t OFF_UF = OFF_ZF + (size_t)B * H;
constexpr size_t OFF_OUF = OFF_UF + (size_t)B * H;

// ---- mma.sync GEMM config (128x256 CTA tile, 512 threads / 16 warps) ----
constexpr int NCH = 22;
constexpr int WIMG = 256 * 64;
constexpr int GA = 0;
constexpr int GB = 8192;
constexpr int GSTAGE = 24576;
constexpr int GS_TOTAL = 2 * GSTAGE;

// ---- rec fallback smem ----
constexpr int REC_WZ_BYTES = 256 * 256 * 2;
constexpr int REC_SMEM = REC_WZ_BYTES + 2 * 2 * 8 * 4 + 64;

// ---- spec rec staging ----
constexpr int STILE = 40;
constexpr int SNT = T / STILE;
constexpr int STILE_BYTES = STILE * H * 2;
constexpr int SPEC_SMEM = 2 * STILE_BYTES;

// ---- segmented ou scan ----
constexpr int NSEG = 50, SEGL = 20;
}  // namespace

__device__ __align__(128) __half g_curx[(size_t)T * B * H];
__device__ uint32_t g_zmask[(size_t)T * B * 8];
__device__ float g_losspart[(size_t)T * B];
__device__ float g_segend[(size_t)NSEG * B * O];
__device__ float g_carry[(size_t)NSEG * B * O];
__device__ int g_spike_flag;
__device__ __align__(128) unsigned char g_wB[NCH * WIMG];

// ---------------------------------------------------------------------------
// helpers
// ---------------------------------------------------------------------------
__device__ __forceinline__ unsigned smem_u32(const void* p) {
  return (unsigned)__cvta_generic_to_shared(p);
}
__device__ __forceinline__ uint32_t pack_half2(float a, float b) {
  __half2 h = __floats2half2_rn(a, b);
  return *reinterpret_cast<uint32_t*>(&h);
}

#define LDSM4(r, addr)                                                        \
  asm volatile("ldmatrix.sync.aligned.m8n8.x4.shared.b16 {%0,%1,%2,%3}, [%4];" \
               : "=r"((r)[0]), "=r"((r)[1]), "=r"((r)[2]), "=r"((r)[3])        \
               : "r"(addr))

#define MMA16816F(d, a, b0, b1)                                               \
  asm volatile(                                                               \
      "mma.sync.aligned.m16n8k16.row.col.f32.f16.f16.f32 "                    \
      "{%0,%1,%2,%3},{%4,%5,%6,%7},{%8,%9},{%0,%1,%2,%3};"                    \
      : "+f"((d)[0]), "+f"((d)[1]), "+f"((d)[2]), "+f"((d)[3])                \
      : "r"((a)[0]), "r"((a)[1]), "r"((a)[2]), "r"((a)[3]), "r"(b0), "r"(b1))

#define CPASYNC16(dst, src)                                                   \
  asm volatile("cp.async.cg.shared.global [%0], [%1], 16;" :: "r"(dst),       \
               "l"(src) : "memory")

// ---------------------------------------------------------------------------
// Kernel 0: W_h[:, :700] -> fp16, pre-swizzled smem-image layout.
// Also resets the spike flag (one thread).
// ---------------------------------------------------------------------------
__global__ void prep_w_kernel(const float* __restrict__ Wh) {
  if (blockIdx.x == 0 && threadIdx.x == 0) g_spike_flag = 0;
  const int chunk = blockIdx.x;
  const int n = threadIdx.x;
  unsigned char* dst = g_wB + (size_t)chunk * WIMG + n * 64;
#pragma unroll
  for (int c = 0; c < 4; ++c) {
    uint32_t u[4];
#pragma unroll
    for (int jj = 0; jj < 4; ++jj) {
      const int k = chunk * 32 + c * 8 + jj * 2;
      float w0 = (k < I) ? Wh[(size_t)n * WHS + k] : 0.f;
      float w1 = (k + 1 < I) ? Wh[(size_t)n * WHS + k + 1] : 0.f;
      u[jj] = pack_half2(w0, w1);
    }
    const int cSw = c ^ ((n >> 1) & 3);
    *reinterpret_cast<uint4*>(dst + cSw * 16) = make_uint4(u[0], u[1], u[2], u[3]);
  }
}

// ---------------------------------------------------------------------------
// Kernel 1: cur_x = x @ W_x^T via mma.sync fp16.
// 512 threads / 16 warps (4m x 4n), warp tile 32x64, acc 64 regs/thread.
// Same MMA ordering as the 256-thread version -> bit-identical results.
// ---------------------------------------------------------------------------
__global__ __launch_bounds__(512, 1) void gemm_mma_kernel(const float* __restrict__ X) {
  extern __shared__ __align__(1024) unsigned char smem[];
  const uint32_t sb = smem_u32(smem);
  const int tid = threadIdx.x;
  const int lane = tid & 31, wid = tid >> 5;
  const int wm = (wid & 3) * 32, wn = (wid >> 2) * 64;
  const int m0 = blockIdx.x * 128;

  // A loader: 4 threads per row; thread covers k-group cgrp (8 halves = 16 B)
  const int arow = tid >> 2;
  const int cgrp = tid & 3;
  const float* xrow = X + (size_t)(m0 + arow) * I + cgrp * 8;
  const uint32_t aXor = ((arow >> 1) & 3);
  const uint32_t aOff = (uint32_t)(arow * 64) + (((uint32_t)cgrp ^ aXor) << 4);

  int raddr[2], sxa[2], rbad[4], sxb[4];
#pragma unroll
  for (int mt = 0; mt < 2; ++mt) {
    int r = wm + mt * 16 + (lane & 15);
    raddr[mt] = r * 64;
    sxa[mt] = (r >> 1) & 3;
  }
  const int ca = lane >> 4;
#pragma unroll
  for (int g = 0; g < 4; ++g) {
    int n = wn + g * 16 + (lane & 7) + ((lane >> 4) << 3);
    rbad[g] = n * 64;
    sxb[g] = (n >> 1) & 3;
  }
  const int cb = (lane >> 3) & 1;

  float acc[2][8][4];
#pragma unroll
  for (int mt = 0; mt < 2; ++mt)
#pragma unroll
    for (int n8 = 0; n8 < 8; ++n8)
#pragma unroll
      for (int j = 0; j < 4; ++j) acc[mt][n8][j] = 0.f;

  float4 av[2];

  // ---- prologue: chunk 0 ----
#pragma unroll
  for (int i = 0; i < 2; ++i) {
    const int col = cgrp * 8 + i * 4;
    av[i] = (col < I) ? *reinterpret_cast<const float4*>(xrow + i * 4)
                      : make_float4(0.f, 0.f, 0.f, 0.f);
  }
  {
#pragma unroll
    for (int i = 0; i < 2; ++i)
      CPASYNC16(sb + GB + tid * 16 + i * 8192, g_wB + tid * 16 + i * 8192);
    asm volatile("cp.async.commit_group;" ::: "memory");
  }
  {
    uint32_t hu[4];
    hu[0] = pack_half2(av[0].x, av[0].y);
    hu[1] = pack_half2(av[0].z, av[0].w);
    hu[2] = pack_half2(av[1].x, av[1].y);
    hu[3] = pack_half2(av[1].z, av[1].w);
    *reinterpret_cast<uint4*>(smem + GA + aOff) = make_uint4(hu[0], hu[1], hu[2], hu[3]);
  }

  // ---- main loop ----
  for (int c = 0; c < NCH; ++c) {
    asm volatile("cp.async.wait_group 0;" ::: "memory");
    __syncthreads();

    const int nc = c + 1;
    if (nc < NCH) {
      const uint32_t nst = sb + (nc & 1) * GSTAGE;
      const unsigned char* src = g_wB + (size_t)nc * WIMG;
#pragma unroll
      for (int i = 0; i < 2; ++i)
        CPASYNC16(nst + GB + tid * 16 + i * 8192, src + tid * 16 + i * 8192);
      asm volatile("cp.async.commit_group;" ::: "memory");
      const int colbase = nc * 32 + cgrp * 8;
#pragma unroll
      for (int i = 0; i < 2; ++i) {
        const int col = colbase + i * 4;
        av[i] = (col < I) ? *reinterpret_cast<const float4*>(xrow + nc * 32 + i * 4)
                          : make_float4(0.f, 0.f, 0.f, 0.f);
      }
    }

    const uint32_t st = sb + (c & 1) * GSTAGE;
#pragma unroll
    for (int k16 = 0; k16 < 2; ++k16) {
      uint32_t ah[2][4], bb[4][4];
      const int kca = k16 * 2 + ca;
      const int kcb = k16 * 2 + cb;
#pragma unroll
      for (int mt = 0; mt < 2; ++mt)
        LDSM4(ah[mt], st + GA + raddr[mt] + (((kca ^ sxa[mt])) << 4));
#pragma unroll
      for (int g = 0; g < 4; ++g)
        LDSM4(bb[g], st + GB + rbad[g] + (((kcb ^ sxb[g])) << 4));
#pragma unroll
      for (int mt = 0; mt < 2; ++mt)
#pragma unroll
        for (int g = 0; g < 4; ++g) {
          MMA16816F(acc[mt][2 * g], ah[mt], bb[g][0], bb[g][1]);
          MMA16816F(acc[mt][2 * g + 1], ah[mt], bb[g][2], bb[g][3]);
        }
    }

    if (nc < NCH) {
      unsigned char* stn = smem + (nc & 1) * GSTAGE;
      uint32_t hu[4];
      hu[0] = pack_half2(av[0].x, av[0].y);
      hu[1] = pack_half2(av[0].z, av[0].w);
      hu[2] = pack_half2(av[1].x, av[1].y);
      hu[3] = pack_half2(av[1].z, av[1].w);
      *reinterpret_cast<uint4*>(stn + GA + aOff) = make_uint4(hu[0], hu[1], hu[2], hu[3]);
    }
  }

  // ---- epilogue: acc -> g_curx (fp16) ----
#pragma unroll
  for (int mt = 0; mt < 2; ++mt) {
    const int r0 = m0 + wm + mt * 16 + (lane >> 2);
#pragma unroll
    for (int n8 = 0; n8 < 8; ++n8) {
      const int col = wn + n8 * 8 + (lane & 3) * 2;
      *reinterpret_cast<__half2*>(g_curx + (size_t)r0 * H + col) =
          __floats2half2_rn(acc[mt][n8][0], acc[mt][n8][1]);
      *reinterpret_cast<__half2*>(g_curx + (size_t)(r0 + 8) * H + col) =
          __floats2half2_rn(acc[mt][n8][2], acc[mt][n8][3]);
    }
  }
}

// ---------------------------------------------------------------------------
// Kernel 2a: SPECULATIVE recurrence — CTA per batch row, cp.async staging.
// ---------------------------------------------------------------------------
__global__ void __launch_bounds__(256, 1)
spec_rec_kernel(const float* __restrict__ omp, const float* __restrict__ bop,
                float* __restrict__ out) {
  extern __shared__ __align__(16) unsigned char ssm[];
  const uint32_t sb = smem_u32(ssm);
  const int tid = threadIdx.x;
  const int b = blockIdx.x;

  const float om = fabsf(omp[tid]);
  const float dmv = DELTA * om;
  const float pom = (-1.f + sqrtf(1.f - dmv * dmv)) / DELTA;
  const float bcoef = pom - fabsf(bop[tid]);

  const unsigned char* base =
      reinterpret_cast<const unsigned char*>(g_curx) + (size_t)b * H * 2;
  const size_t rowb = (size_t)B * H * 2;

  auto issue = [&](int tile, int buf) {
    const unsigned char* src = base + (size_t)tile * STILE * rowb;
#pragma unroll
    for (int p = 0; p < 5; ++p) {
      const int o = (p * 256 + tid) * 16;
      const int s = o >> 9, byt = o & 511;
      CPASYNC16(sb + buf * STILE_BYTES + o, src + (size_t)s * rowb + byt);
    }
    asm volatile("cp.async.commit_group;" ::: "memory");
  };

  issue(0, 0);
  float u = 0.f, v = 0.f, umax = -1e30f;

  for (int tile = 0; tile < SNT; ++tile) {
    if (tile + 1 < SNT) {
      issue(tile + 1, (tile + 1) & 1);
      asm volatile("cp.async.wait_group 1;" ::: "memory");
    } else {
      asm volatile("cp.async.wait_group 0;" ::: "memory");
    }
    __syncthreads();
    const __half* hs =
        reinterpret_cast<const __half*>(ssm + (tile & 1) * STILE_BYTES);
#pragma unroll 8
    for (int s = 0; s < STILE; ++s) {
      const float cw = __half2float(hs[s * H + tid]);
      const float un = u + DELTA * (bcoef * u - om * v + cw);
      const float vn = v + DELTA * (om * un + bcoef * v);
      umax = fmaxf(umax, un);
      u = un; v = vn;
    }
    __syncthreads();
  }

  if ((umax - THETA) > 0.f) g_spike_flag = 1;
  out[OFF_UF + (size_t)b * H + tid] = u;
  out[OFF_ZF + (size_t)b * H + tid] = 0.f;
}

// ---------------------------------------------------------------------------
// Kernel 2b: serial fallback (exact, handles spikes). Early-exits when the
// speculation succeeded. Writes every zmask word itself.
// ---------------------------------------------------------------------------
__global__ void __launch_bounds__(256, 1)
rec_fallback_kernel(const float* __restrict__ Wh, const float* __restrict__ omp,
                    const float* __restrict__ bop, float* __restrict__ out) {
  if (g_spike_flag == 0) return;
  extern __shared__ unsigned char smrec[];
  __half* Wz = reinterpret_cast<__half*>(smrec);
  uint32_t* zms = reinterpret_cast<uint32_t*>(smrec + REC_WZ_BYTES);

  const int tid = threadIdx.x;
  const int lane = tid & 31;
  const int wq = tid >> 5;
  const int b0 = blockIdx.x * 2;

  {
    const float* src = Wh + (size_t)tid * WHS + I;
#pragma unroll 8
    for (int j = 0; j < 256; ++j) Wz[j * 256 + tid] = __float2half(src[j]);
  }
  if (tid < 32) zms[tid] = 0u;

  const float om = fabsf(omp[tid]);
  const float dmv = DELTA * om;
  const float pom = (-1.f + sqrtf(1.f - dmv * dmv)) / DELTA;
  const float bof = fabsf(bop[tid]);
  float u[2] = {0, 0}, v[2] = {0, 0}, q[2] = {0, 0}, zr[2] = {0, 0};

  __syncthreads();

  for (int t = 0; t < T; ++t) {
    const int cbuf = t & 1, nbuf = cbuf ^ 1;
    const __half* cp = g_curx + ((size_t)t * B + b0) * H + tid;
    float a0 = __half2float(cp[0]), a1 = __half2float(cp[H]);

#pragma unroll
    for (int w = 0; w < 8; ++w) {
      uint32_t m = zms[(cbuf * 2 + 0) * 8 + w];
      while (m) {
        int bp = __ffs(m) - 1; m &= m - 1;
        a0 += __half2float(Wz[((w << 5) + bp) * 256 + tid]);
      }
    }
#pragma unroll
    for (int w = 0; w < 8; ++w) {
      uint32_t m = zms[(cbuf * 2 + 1) * 8 + w];
      while (m) {
        int bp = __ffs(m) - 1; m &= m - 1;
        a1 += __half2float(Wz[((w << 5) + bp) * 256 + tid]);
      }
    }

#pragma unroll
    for (int rr = 0; rr < 2; ++rr) {
      const float cw = rr ? a1 : a0;
      float b = pom - bof - q[rr];
      float un = u[rr] + DELTA * (b * u[rr] - om * v[rr] + cw);
      float vn = v[rr] + DELTA * (om * un + b * v[rr]);
      float z = (un - THETA - q[rr]) > 0.f ? 1.f : 0.f;
      q[rr] = GAMMA * q[rr] + z;
      u[rr] = un; v[rr] = vn; zr[rr] = z;
    }

    const unsigned mk0 = __ballot_sync(0xffffffffu, zr[0] > 0.f);
    const unsigned mk1 = __ballot_sync(0xffffffffu, zr[1] > 0.f);
    if (lane == 0) {
      zms[(nbuf * 2 + 0) * 8 + wq] = mk0;
      zms[(nbuf * 2 + 1) * 8 + wq] = mk1;
      g_zmask[((size_t)t * B + b0) * 8 + wq] = mk0;
      g_zmask[((size_t)t * B + b0 + 1) * 8 + wq] = mk1;
    }
    __syncthreads();
  }

#pragma unroll
  for (int rr = 0; rr < 2; ++rr) {
    const size_t idx = (size_t)(b0 + rr) * H + tid;
    out[OFF_ZF + idx] = zr[rr];
    out[OFF_UF + idx] = u[rr];
  }
}

// ---------------------------------------------------------------------------
// Kernel 3a: segment-local ou scan; zero fast path when no spikes.
// ---------------------------------------------------------------------------
__global__ void __launch_bounds__(256, 1)
scan_seg_kernel(const float* __restrict__ Wo, const float* __restrict__ taup,
                float* __restrict__ out) {
  const int tid = threadIdx.x;
  const int lid = tid & 31;
  const int gw = blockIdx.x * 8 + (tid >> 5);
  const int b = gw & (B - 1);
  const int seg = gw >> 8;
  const int t0 = seg * SEGL;

  if (g_spike_flag == 0) {
    if (lid < 20) {
      for (int k = 0; k < SEGL; ++k)
        out[((size_t)(t0 + k) * B + b) * O + lid] = 0.f;
      g_segend[((size_t)seg * B + b) * O + lid] = 0.f;
    }
    return;
  }

  __shared__ float WoT[256 * 20 + 32];
  for (int i = tid; i < 256 * 20; i += 256) {
    const int j = i / 20, o = i - j * 20;
    WoT[i] = Wo[o * H + j];
  }
  __syncthreads();

  const float alpha = (lid < 20) ? expf(-DELTA / taup[lid]) : 0.f;
  const float onem = 1.f - alpha;
  float l = 0.f;

  uint32_t mw = (lid < 8) ? g_zmask[((size_t)t0 * B + b) * 8 + lid] : 0u;
  for (int k = 0; k < SEGL; ++k) {
    const int t = t0 + k;
    uint32_t mwn = 0u;
    if (k + 1 < SEGL && lid < 8)
      mwn = g_zmask[((size_t)(t + 1) * B + b) * 8 + lid];
    float s = 0.f;
#pragma unroll
    for (int w = 0; w < 8; ++w) {
      uint32_t word = __shfl_sync(0xffffffffu, mw, w);
      while (word) {
        int bp = __ffs(word) - 1; word &= word - 1;
        s += WoT[((w << 5) + bp) * 20 + lid];
      }
    }
    l = alpha * l + onem * s;
    if (lid < 20) out[((size_t)t * B + b) * O + lid] = l;
    mw = mwn;
  }
  if (lid < 20) g_segend[((size_t)seg * B + b) * O + lid] = l;
}

// ---------------------------------------------------------------------------
// Kernel 3b: serial carry over segments, writes ouf. Zero fast path.
// ---------------------------------------------------------------------------
__global__ void __launch_bounds__(256)
carry_kernel(const float* __restrict__ taup, float* __restrict__ out) {
  const int idx = blockIdx.x * 256 + threadIdx.x;
  if (idx >= B * O) return;
  if (g_spike_flag == 0) {
    out[OFF_OUF + idx] = 0.f;
    return;
  }
  const int b = idx / O, o = idx - b * O;
  const float aL = expf(-DELTA * (float)SEGL / taup[o]);
  float c = 0.f;
  for (int s = 0; s < NSEG; ++s) {
    g_carry[((size_t)s * B + b) * O + o] = c;
    c = c * aL + g_segend[((size_t)s * B + b) * O + o];
  }
  out[OFF_OUF + (size_t)b * O + o] = c;
}

// ---------------------------------------------------------------------------
// Kernel 3c: fixup — no-op when no spikes (carry all zero).
// ---------------------------------------------------------------------------
__global__ void __launch_bounds__(256)
fixup_kernel(const float* __restrict__ taup, float* __restrict__ out) {
  if (g_spike_flag == 0) return;
  const int idx = blockIdx.x * 256 + threadIdx.x;
  if (idx >= T * B * O) return;
  const int o = idx % O;
  const int tb = idx / O;
  const int t = tb / B, b = tb - t * B;
  const int seg = t / SEGL, k = t - seg * SEGL;
  const float c = g_carry[((size_t)seg * B + b) * O + o];
  if (c != 0.f) {
    const float alpha = expf(-DELTA / taup[o]);
    out[idx] += powf(alpha, (float)(k + 1)) * c;
  }
}

// ---------------------------------------------------------------------------
// Kernel 4: per-(t,b) log-softmax loss partials; constant fast path.
// ---------------------------------------------------------------------------
__global__ void __launch_bounds__(256)
loss_kernel(const int* __restrict__ Y, const float* __restrict__ out) {
  const int idx = blockIdx.x * 256 + threadIdx.x;
  if (idx >= T * B) return;
  if (g_spike_flag == 0) {
    g_losspart[idx] = logf(20.f) * (1.f / (float)B);
    return;
  }
  const float* o20 = out + (size_t)idx * O;
  const int y = Y[idx];
  float m = -1e30f;
#pragma unroll
  for (int o = 0; o < O; ++o) m = fmaxf(m, o20[o]);
  float se = 0.f;
#pragma unroll
  for (int o = 0; o < O; ++o) se += expf(o20[o] - m);
  g_losspart[idx] = -(o20[y] - m - logf(se)) * (1.f / (float)B);
}

// ---------------------------------------------------------------------------
// Kernel 5: deterministic loss reduction.
// ---------------------------------------------------------------------------
__global__ void __launch_bounds__(1024) reduce_kernel(float* __restrict__ out) {
  __shared__ float s[1024];
  float acc = 0.f;
  for (int i = threadIdx.x; i < T * B; i += 1024) acc += g_losspart[i];
  s[threadIdx.x] = acc;
  __syncthreads();
  for (int st = 512; st > 0; st >>= 1) {
    if (threadIdx.x < st) s[threadIdx.x] += s[threadIdx.x + st];
    __syncthreads();
  }
  if (threadIdx.x == 0) out[OFF_LOSS] = s[0];
}

// ---------------------------------------------------------------------------
extern "C" void kernel_launch(void* const* d_in, const int* in_sizes, int n_in,
                              void* d_out, int out_size) {
  const float* x = (const float*)d_in[0];
  const int* y = (const int*)d_in[1];
  const float* Wh = (const float*)d_in[2];
  const float* omega = (const float*)d_in[3];
  const float* boff = (const float*)d_in[4];
  const float* Wo = (const float*)d_in[5];
  const float* tau = (const float*)d_in[6];
  float* out = (float*)d_out;

  cudaFuncSetAttribute(gemm_mma_kernel, cudaFuncAttributeMaxDynamicSharedMemorySize,
                       GS_TOTAL);
  cudaFuncSetAttribute(rec_fallback_kernel, cudaFuncAttributeMaxDynamicSharedMemorySize,
                       REC_SMEM);
  cudaFuncSetAttribute(spec_rec_kernel, cudaFuncAttributeMaxDynamicSharedMemorySize,
                       SPEC_SMEM);

  prep_w_kernel<<<NCH, 256>>>(Wh);
  gemm_mma_kernel<<<(T * B) / 128, 512, GS_TOTAL>>>(x);
  spec_rec_kernel<<<B, 256, SPEC_SMEM>>>(omega, boff, out);
  rec_fallback_kernel<<<B / 2, 256, REC_SMEM>>>(Wh, omega, boff, out);
  scan_seg_kernel<<<NSEG * B / 8, 256>>>(Wo, tau, out);
  carry_kernel<<<(B * O + 255) / 256, 256>>>(tau, out);
  fixup_kernel<<<(T * B * O + 255) / 256, 256>>>(tau, out);
  loss_kernel<<<(T * B + 255) / 256, 256>>>(y, out);
  reduce_kernel<<<1, 1024>>>(out);
}

// round 17
// speedup vs baseline: 1.4230x; 1.0517x over previous
#include <cuda_runtime.h>
#include <cuda_fp16.h>
#include <cstdint>
#include <cstddef>

namespace {
constexpr int T = 1000, B = 256, I = 700, H = 256, O = 20, WHS = I + H;
constexpr float DELTA = 0.01f, GAMMA = 0.9f, THETA = 1.0f;
constexpr size_t OFF_LOSS = (size_t)T * B * O;
constexpr size_t OFF_ZF = OFF_LOSS + 1;
constexpr size_t OFF_UF = OFF_ZF + (size_t)B * H;
constexpr size_t OFF_OUF = OFF_UF + (size_t)B * H;

// ---- mma.sync GEMM config (128x256 CTA tile, 512 threads / 16 warps) ----
constexpr int NCH = 22;
constexpr int WIMG = 256 * 64;
constexpr int GA = 0;
constexpr int GB = 8192;
constexpr int GSTAGE = 24576;
constexpr int EP_STRIDE = 264;                       // halves per padded row
constexpr int GS_DYN = 128 * EP_STRIDE * 2;          // 67584 > 2*GSTAGE
static_assert(GS_DYN >= 2 * GSTAGE, "epilogue region must cover stages");

// ---- rec fallback smem ----
constexpr int REC_WZ_BYTES = 256 * 256 * 2;
constexpr int REC_SMEM = REC_WZ_BYTES + 2 * 2 * 8 * 4 + 64;

// ---- spec rec staging ----
constexpr int STILE = 40;
constexpr int SNT = T / STILE;
constexpr int STILE_BYTES = STILE * H * 2;
constexpr int SPEC_SMEM = 2 * STILE_BYTES;

// ---- segmented ou scan ----
constexpr int NSEG = 50, SEGL = 20;
}  // namespace

__device__ __align__(128) __half g_curx[(size_t)T * B * H];
__device__ uint32_t g_zmask[(size_t)T * B * 8];
__device__ float g_losspart[(size_t)T * B];
__device__ float g_segend[(size_t)NSEG * B * O];
__device__ float g_carry[(size_t)NSEG * B * O];
__device__ int g_spike_flag;
__device__ __align__(128) unsigned char g_wB[NCH * WIMG];

// ---------------------------------------------------------------------------
// helpers
// ---------------------------------------------------------------------------
__device__ __forceinline__ unsigned smem_u32(const void* p) {
  return (unsigned)__cvta_generic_to_shared(p);
}
__device__ __forceinline__ uint32_t pack_half2(float a, float b) {
  __half2 h = __floats2half2_rn(a, b);
  return *reinterpret_cast<uint32_t*>(&h);
}

#define LDSM4(r, addr)                                                        \
  asm volatile("ldmatrix.sync.aligned.m8n8.x4.shared.b16 {%0,%1,%2,%3}, [%4];" \
               : "=r"((r)[0]), "=r"((r)[1]), "=r"((r)[2]), "=r"((r)[3])        \
               : "r"(addr))

#define MMA16816F(d, a, b0, b1)                                               \
  asm volatile(                                                               \
      "mma.sync.aligned.m16n8k16.row.col.f32.f16.f16.f32 "                    \
      "{%0,%1,%2,%3},{%4,%5,%6,%7},{%8,%9},{%0,%1,%2,%3};"                    \
      : "+f"((d)[0]), "+f"((d)[1]), "+f"((d)[2]), "+f"((d)[3])                \
      : "r"((a)[0]), "r"((a)[1]), "r"((a)[2]), "r"((a)[3]), "r"(b0), "r"(b1))

#define CPASYNC16(dst, src)                                                   \
  asm volatile("cp.async.cg.shared.global [%0], [%1], 16;" :: "r"(dst),       \
               "l"(src) : "memory")

// ---------------------------------------------------------------------------
// Kernel 0: W prep + flag reset.
// ---------------------------------------------------------------------------
__global__ void prep_w_kernel(const float* __restrict__ Wh) {
  if (blockIdx.x == 0 && threadIdx.x == 0) g_spike_flag = 0;
  const int chunk = blockIdx.x;
  const int n = threadIdx.x;
  unsigned char* dst = g_wB + (size_t)chunk * WIMG + n * 64;
#pragma unroll
  for (int c = 0; c < 4; ++c) {
    uint32_t u[4];
#pragma unroll
    for (int jj = 0; jj < 4; ++jj) {
      const int k = chunk * 32 + c * 8 + jj * 2;
      float w0 = (k < I) ? Wh[(size_t)n * WHS + k] : 0.f;
      float w1 = (k + 1 < I) ? Wh[(size_t)n * WHS + k + 1] : 0.f;
      u[jj] = pack_half2(w0, w1);
    }
    const int cSw = c ^ ((n >> 1) & 3);
    *reinterpret_cast<uint4*>(dst + cSw * 16) = make_uint4(u[0], u[1], u[2], u[3]);
  }
}

// ---------------------------------------------------------------------------
// Kernel 1: cur_x = x @ W_x^T via mma.sync fp16, 512 thr / 16 warps.
// Epilogue stages the fp16 tile through smem for coalesced 512B/warp stores.
// ---------------------------------------------------------------------------
__global__ __launch_bounds__(512, 1) void gemm_mma_kernel(const float* __restrict__ X) {
  extern __shared__ __align__(1024) unsigned char smem[];
  const uint32_t sb = smem_u32(smem);
  const int tid = threadIdx.x;
  const int lane = tid & 31, wid = tid >> 5;
  const int wm = (wid & 3) * 32, wn = (wid >> 2) * 64;
  const int m0 = blockIdx.x * 128;

  const int arow = tid >> 2;
  const int cgrp = tid & 3;
  const float* xrow = X + (size_t)(m0 + arow) * I + cgrp * 8;
  const uint32_t aXor = ((arow >> 1) & 3);
  const uint32_t aOff = (uint32_t)(arow * 64) + (((uint32_t)cgrp ^ aXor) << 4);

  int raddr[2], sxa[2], rbad[4], sxb[4];
#pragma unroll
  for (int mt = 0; mt < 2; ++mt) {
    int r = wm + mt * 16 + (lane & 15);
    raddr[mt] = r * 64;
    sxa[mt] = (r >> 1) & 3;
  }
  const int ca = lane >> 4;
#pragma unroll
  for (int g = 0; g < 4; ++g) {
    int n = wn + g * 16 + (lane & 7) + ((lane >> 4) << 3);
    rbad[g] = n * 64;
    sxb[g] = (n >> 1) & 3;
  }
  const int cb = (lane >> 3) & 1;

  float acc[2][8][4];
#pragma unroll
  for (int mt = 0; mt < 2; ++mt)
#pragma unroll
    for (int n8 = 0; n8 < 8; ++n8)
#pragma unroll
      for (int j = 0; j < 4; ++j) acc[mt][n8][j] = 0.f;

  float4 av[2];

#pragma unroll
  for (int i = 0; i < 2; ++i) {
    const int col = cgrp * 8 + i * 4;
    av[i] = (col < I) ? *reinterpret_cast<const float4*>(xrow + i * 4)
                      : make_float4(0.f, 0.f, 0.f, 0.f);
  }
  {
#pragma unroll
    for (int i = 0; i < 2; ++i)
      CPASYNC16(sb + GB + tid * 16 + i * 8192, g_wB + tid * 16 + i * 8192);
    asm volatile("cp.async.commit_group;" ::: "memory");
  }
  {
    uint32_t hu[4];
    hu[0] = pack_half2(av[0].x, av[0].y);
    hu[1] = pack_half2(av[0].z, av[0].w);
    hu[2] = pack_half2(av[1].x, av[1].y);
    hu[3] = pack_half2(av[1].z, av[1].w);
    *reinterpret_cast<uint4*>(smem + GA + aOff) = make_uint4(hu[0], hu[1], hu[2], hu[3]);
  }

  for (int c = 0; c < NCH; ++c) {
    asm volatile("cp.async.wait_group 0;" ::: "memory");
    __syncthreads();

    const int nc = c + 1;
    if (nc < NCH) {
      const uint32_t nst = sb + (nc & 1) * GSTAGE;
      const unsigned char* src = g_wB + (size_t)nc * WIMG;
#pragma unroll
      for (int i = 0; i < 2; ++i)
        CPASYNC16(nst + GB + tid * 16 + i * 8192, src + tid * 16 + i * 8192);
      asm volatile("cp.async.commit_group;" ::: "memory");
      const int colbase = nc * 32 + cgrp * 8;
#pragma unroll
      for (int i = 0; i < 2; ++i) {
        const int col = colbase + i * 4;
        av[i] = (col < I) ? *reinterpret_cast<const float4*>(xrow + nc * 32 + i * 4)
                          : make_float4(0.f, 0.f, 0.f, 0.f);
      }
    }

    const uint32_t st = sb + (c & 1) * GSTAGE;
#pragma unroll
    for (int k16 = 0; k16 < 2; ++k16) {
      uint32_t ah[2][4], bb[4][4];
      const int kca = k16 * 2 + ca;
      const int kcb = k16 * 2 + cb;
#pragma unroll
      for (int mt = 0; mt < 2; ++mt)
        LDSM4(ah[mt], st + GA + raddr[mt] + (((kca ^ sxa[mt])) << 4));
#pragma unroll
      for (int g = 0; g < 4; ++g)
        LDSM4(bb[g], st + GB + rbad[g] + (((kcb ^ sxb[g])) << 4));
#pragma unroll
      for (int mt = 0; mt < 2; ++mt)
#pragma unroll
        for (int g = 0; g < 4; ++g) {
          MMA16816F(acc[mt][2 * g], ah[mt], bb[g][0], bb[g][1]);
          MMA16816F(acc[mt][2 * g + 1], ah[mt], bb[g][2], bb[g][3]);
        }
    }

    if (nc < NCH) {
      unsigned char* stn = smem + (nc & 1) * GSTAGE;
      uint32_t hu[4];
      hu[0] = pack_half2(av[0].x, av[0].y);
      hu[1] = pack_half2(av[0].z, av[0].w);
      hu[2] = pack_half2(av[1].x, av[1].y);
      hu[3] = pack_half2(av[1].z, av[1].w);
      *reinterpret_cast<uint4*>(stn + GA + aOff) = make_uint4(hu[0], hu[1], hu[2], hu[3]);
    }
  }

  // ---- epilogue: acc -> smem (fp16, padded) -> coalesced STG ----
  __syncthreads();
  {
    __half* eps = reinterpret_cast<__half*>(smem);
#pragma unroll
    for (int mt = 0; mt < 2; ++mt) {
      const int r0 = wm + mt * 16 + (lane >> 2);
#pragma unroll
      for (int n8 = 0; n8 < 8; ++n8) {
        const int col = wn + n8 * 8 + (lane & 3) * 2;
        *reinterpret_cast<__half2*>(eps + r0 * EP_STRIDE + col) =
            __floats2half2_rn(acc[mt][n8][0], acc[mt][n8][1]);
        *reinterpret_cast<__half2*>(eps + (r0 + 8) * EP_STRIDE + col) =
            __floats2half2_rn(acc[mt][n8][2], acc[mt][n8][3]);
      }
    }
  }
  __syncthreads();
  {
    const __half* eps = reinterpret_cast<const __half*>(smem);
#pragma unroll
    for (int i = 0; i < 8; ++i) {
      const int idx = tid + i * 512;       // 0..4095
      const int row = idx >> 5, seg = idx & 31;
      *reinterpret_cast<uint4*>(g_curx + (size_t)(m0 + row) * H + seg * 8) =
          *reinterpret_cast<const uint4*>(eps + row * EP_STRIDE + seg * 8);
    }
  }
}

// ---------------------------------------------------------------------------
// Kernel 2a: SPECULATIVE recurrence — CTA per batch row, cp.async staging.
// Recurrence in fused form: un = A*u - E*v + dc; vn = A*v + E*un.
// ---------------------------------------------------------------------------
__global__ void __launch_bounds__(256, 1)
spec_rec_kernel(const float* __restrict__ omp, const float* __restrict__ bop,
                float* __restrict__ out) {
  extern __shared__ __align__(16) unsigned char ssm[];
  const uint32_t sb = smem_u32(ssm);
  const int tid = threadIdx.x;
  const int b = blockIdx.x;

  const float om = fabsf(omp[tid]);
  const float dmv = DELTA * om;
  const float pom = (-1.f + sqrtf(1.f - dmv * dmv)) / DELTA;
  const float bcoef = pom - fabsf(bop[tid]);
  const float A = 1.f + DELTA * bcoef;
  const float E = DELTA * om;

  const unsigned char* base =
      reinterpret_cast<const unsigned char*>(g_curx) + (size_t)b * H * 2;
  const size_t rowb = (size_t)B * H * 2;

  auto issue = [&](int tile, int buf) {
    const unsigned char* src = base + (size_t)tile * STILE * rowb;
#pragma unroll
    for (int p = 0; p < 5; ++p) {
      const int o = (p * 256 + tid) * 16;
      const int s = o >> 9, byt = o & 511;
      CPASYNC16(sb + buf * STILE_BYTES + o, src + (size_t)s * rowb + byt);
    }
    asm volatile("cp.async.commit_group;" ::: "memory");
  };

  issue(0, 0);
  float u = 0.f, v = 0.f, umax = -1e30f;

  for (int tile = 0; tile < SNT; ++tile) {
    if (tile + 1 < SNT) {
      issue(tile + 1, (tile + 1) & 1);
      asm volatile("cp.async.wait_group 1;" ::: "memory");
    } else {
      asm volatile("cp.async.wait_group 0;" ::: "memory");
    }
    __syncthreads();
    const __half* hs =
        reinterpret_cast<const __half*>(ssm + (tile & 1) * STILE_BYTES);
#pragma unroll 8
    for (int s = 0; s < STILE; ++s) {
      const float dc = DELTA * __half2float(hs[s * H + tid]);
      const float un = fmaf(A, u, fmaf(-E, v, dc));
      const float vn = fmaf(A, v, E * un);
      umax = fmaxf(umax, un);
      u = un; v = vn;
    }
    __syncthreads();
  }

  if ((umax - THETA) > 0.f) g_spike_flag = 1;
  out[OFF_UF + (size_t)b * H + tid] = u;
  out[OFF_ZF + (size_t)b * H + tid] = 0.f;
}

// ---------------------------------------------------------------------------
// Kernel 2b: serial fallback (exact, handles spikes). Early-exits when the
// speculation succeeded. Writes every zmask word itself.
// ---------------------------------------------------------------------------
__global__ void __launch_bounds__(256, 1)
rec_fallback_kernel(const float* __restrict__ Wh, const float* __restrict__ omp,
                    const float* __restrict__ bop, float* __restrict__ out) {
  if (g_spike_flag == 0) return;
  extern __shared__ unsigned char smrec[];
  __half* Wz = reinterpret_cast<__half*>(smrec);
  uint32_t* zms = reinterpret_cast<uint32_t*>(smrec + REC_WZ_BYTES);

  const int tid = threadIdx.x;
  const int lane = tid & 31;
  const int wq = tid >> 5;
  const int b0 = blockIdx.x * 2;

  {
    const float* src = Wh + (size_t)tid * WHS + I;
#pragma unroll 8
    for (int j = 0; j < 256; ++j) Wz[j * 256 + tid] = __float2half(src[j]);
  }
  if (tid < 32) zms[tid] = 0u;

  const float om = fabsf(omp[tid]);
  const float dmv = DELTA * om;
  const float pom = (-1.f + sqrtf(1.f - dmv * dmv)) / DELTA;
  const float bof = fabsf(bop[tid]);
  float u[2] = {0, 0}, v[2] = {0, 0}, q[2] = {0, 0}, zr[2] = {0, 0};

  __syncthreads();

  for (int t = 0; t < T; ++t) {
    const int cbuf = t & 1, nbuf = cbuf ^ 1;
    const __half* cp = g_curx + ((size_t)t * B + b0) * H + tid;
    float a0 = __half2float(cp[0]), a1 = __half2float(cp[H]);

#pragma unroll
    for (int w = 0; w < 8; ++w) {
      uint32_t m = zms[(cbuf * 2 + 0) * 8 + w];
      while (m) {
        int bp = __ffs(m) - 1; m &= m - 1;
        a0 += __half2float(Wz[((w << 5) + bp) * 256 + tid]);
      }
    }
#pragma unroll
    for (int w = 0; w < 8; ++w) {
      uint32_t m = zms[(cbuf * 2 + 1) * 8 + w];
      while (m) {
        int bp = __ffs(m) - 1; m &= m - 1;
        a1 += __half2float(Wz[((w << 5) + bp) * 256 + tid]);
      }
    }

#pragma unroll
    for (int rr = 0; rr < 2; ++rr) {
      const float cw = rr ? a1 : a0;
      float b = pom - bof - q[rr];
      float un = u[rr] + DELTA * (b * u[rr] - om * v[rr] + cw);
      float vn = v[rr] + DELTA * (om * un + b * v[rr]);
      float z = (un - THETA - q[rr]) > 0.f ? 1.f : 0.f;
      q[rr] = GAMMA * q[rr] + z;
      u[rr] = un; v[rr] = vn; zr[rr] = z;
    }

    const unsigned mk0 = __ballot_sync(0xffffffffu, zr[0] > 0.f);
    const unsigned mk1 = __ballot_sync(0xffffffffu, zr[1] > 0.f);
    if (lane == 0) {
      zms[(nbuf * 2 + 0) * 8 + wq] = mk0;
      zms[(nbuf * 2 + 1) * 8 + wq] = mk1;
      g_zmask[((size_t)t * B + b0) * 8 + wq] = mk0;
      g_zmask[((size_t)t * B + b0 + 1) * 8 + wq] = mk1;
    }
    __syncthreads();
  }

#pragma unroll
  for (int rr = 0; rr < 2; ++rr) {
    const size_t idx = (size_t)(b0 + rr) * H + tid;
    out[OFF_ZF + idx] = zr[rr];
    out[OFF_UF + idx] = u[rr];
  }
}

// ---------------------------------------------------------------------------
// Kernel F: fast-path finalize — when no spikes, writes outputs=0, ouf=0,
// and the exact loss. (Bit-exact up to summation association on the loss.)
// ---------------------------------------------------------------------------
__global__ void __launch_bounds__(256)
fast_finalize_kernel(float* __restrict__ out) {
  if (g_spike_flag != 0) return;
  const int idx = blockIdx.x * 256 + threadIdx.x;
  float4* o4 = reinterpret_cast<float4*>(out);
  if (idx < (int)(T * B * O / 4))
    o4[idx] = make_float4(0.f, 0.f, 0.f, 0.f);
  if (idx < B * O) out[OFF_OUF + idx] = 0.f;
  if (idx == 0) out[OFF_LOSS] = (float)T * logf(20.f);
}

// ---------------------------------------------------------------------------
// Kernels 3a-5: general path only (early-return when no spikes).
// ---------------------------------------------------------------------------
__global__ void __launch_bounds__(256, 1)
scan_seg_kernel(const float* __restrict__ Wo, const float* __restrict__ taup,
                float* __restrict__ out) {
  if (g_spike_flag == 0) return;
  __shared__ float WoT[256 * 20 + 32];
  const int tid = threadIdx.x;
  for (int i = tid; i < 256 * 20; i += 256) {
    const int j = i / 20, o = i - j * 20;
    WoT[i] = Wo[o * H + j];
  }
  __syncthreads();

  const int lid = tid & 31;
  const int gw = blockIdx.x * 8 + (tid >> 5);
  const int b = gw & (B - 1);
  const int seg = gw >> 8;
  const int t0 = seg * SEGL;
  const float alpha = (lid < 20) ? expf(-DELTA / taup[lid]) : 0.f;
  const float onem = 1.f - alpha;
  float l = 0.f;

  uint32_t mw = (lid < 8) ? g_zmask[((size_t)t0 * B + b) * 8 + lid] : 0u;
  for (int k = 0; k < SEGL; ++k) {
    const int t = t0 + k;
    uint32_t mwn = 0u;
    if (k + 1 < SEGL && lid < 8)
      mwn = g_zmask[((size_t)(t + 1) * B + b) * 8 + lid];
    float s = 0.f;
#pragma unroll
    for (int w = 0; w < 8; ++w) {
      uint32_t word = __shfl_sync(0xffffffffu, mw, w);
      while (word) {
        int bp = __ffs(word) - 1; word &= word - 1;
        s += WoT[((w << 5) + bp) * 20 + lid];
      }
    }
    l = alpha * l + onem * s;
    if (lid < 20) out[((size_t)t * B + b) * O + lid] = l;
    mw = mwn;
  }
  if (lid < 20) g_segend[((size_t)seg * B + b) * O + lid] = l;
}

__global__ void __launch_bounds__(256)
carry_kernel(const float* __restrict__ taup, float* __restrict__ out) {
  if (g_spike_flag == 0) return;
  const int idx = blockIdx.x * 256 + threadIdx.x;
  if (idx >= B * O) return;
  const int b = idx / O, o = idx - b * O;
  const float aL = expf(-DELTA * (float)SEGL / taup[o]);
  float c = 0.f;
  for (int s = 0; s < NSEG; ++s) {
    g_carry[((size_t)s * B + b) * O + o] = c;
    c = c * aL + g_segend[((size_t)s * B + b) * O + o];
  }
  out[OFF_OUF + (size_t)b * O + o] = c;
}

__global__ void __launch_bounds__(256)
fixup_kernel(const float* __restrict__ taup, float* __restrict__ out) {
  if (g_spike_flag == 0) return;
  const int idx = blockIdx.x * 256 + threadIdx.x;
  if (idx >= T * B * O) return;
  const int o = idx % O;
  const int tb = idx / O;
  const int t = tb / B, b = tb - t * B;
  const int seg = t / SEGL, k = t - seg * SEGL;
  const float c = g_carry[((size_t)seg * B + b) * O + o];
  if (c != 0.f) {
    const float alpha = expf(-DELTA / taup[o]);
    out[idx] += powf(alpha, (float)(k + 1)) * c;
  }
}

__global__ void __launch_bounds__(256)
loss_kernel(const int* __restrict__ Y, const float* __restrict__ out) {
  if (g_spike_flag == 0) return;
  const int idx = blockIdx.x * 256 + threadIdx.x;
  if (idx >= T * B) return;
  const float* o20 = out + (size_t)idx * O;
  const int y = Y[idx];
  float m = -1e30f;
#pragma unroll
  for (int o = 0; o < O; ++o) m = fmaxf(m, o20[o]);
  float se = 0.f;
#pragma unroll
  for (int o = 0; o < O; ++o) se += expf(o20[o] - m);
  g_losspart[idx] = -(o20[y] - m - logf(se)) * (1.f / (float)B);
}

__global__ void __launch_bounds__(1024) reduce_kernel(float* __restrict__ out) {
  if (g_spike_flag == 0) return;
  __shared__ float s[1024];
  float acc = 0.f;
  for (int i = threadIdx.x; i < T * B; i += 1024) acc += g_losspart[i];
  s[threadIdx.x] = acc;
  __syncthreads();
  for (int st = 512; st > 0; st >>= 1) {
    if (threadIdx.x < st) s[threadIdx.x] += s[threadIdx.x + st];
    __syncthreads();
  }
  if (threadIdx.x == 0) out[OFF_LOSS] = s[0];
}

// ---------------------------------------------------------------------------
extern "C" void kernel_launch(void* const* d_in, const int* in_sizes, int n_in,
                              void* d_out, int out_size) {
  const float* x = (const float*)d_in[0];
  const int* y = (const int*)d_in[1];
  const float* Wh = (const float*)d_in[2];
  const float* omega = (const float*)d_in[3];
  const float* boff = (const float*)d_in[4];
  const float* Wo = (const float*)d_in[5];
  const float* tau = (const float*)d_in[6];
  float* out = (float*)d_out;

  cudaFuncSetAttribute(gemm_mma_kernel, cudaFuncAttributeMaxDynamicSharedMemorySize,
                       GS_DYN);
  cudaFuncSetAttribute(rec_fallback_kernel, cudaFuncAttributeMaxDynamicSharedMemorySize,
                       REC_SMEM);
  cudaFuncSetAttribute(spec_rec_kernel, cudaFuncAttributeMaxDynamicSharedMemorySize,
                       SPEC_SMEM);

  prep_w_kernel<<<NCH, 256>>>(Wh);
  gemm_mma_kernel<<<(T * B) / 128, 512, GS_DYN>>>(x);
  spec_rec_kernel<<<B, 256, SPEC_SMEM>>>(omega, boff, out);
  rec_fallback_kernel<<<B / 2, 256, REC_SMEM>>>(Wh, omega, boff, out);
  fast_finalize_kernel<<<(T * B * O / 4 + 255) / 256, 256>>>(out);
  scan_seg_kernel<<<NSEG * B / 8, 256>>>(Wo, tau, out);
  carry_kernel<<<(B * O + 255) / 256, 256>>>(tau, out);
  fixup_kernel<<<(T * B * O + 255) / 256, 256>>>(tau, out);
  loss_kernel<<<(T * B + 255) / 256, 256>>>(y, out);
  reduce_kernel<<<1, 1024>>>(out);
}